// round 1
// baseline (speedup 1.0000x reference)
#include <cuda_runtime.h>
#include <cstdint>

// Problem constants (fixed-shape problem).
constexpr int N_PTS    = 1048576;          // points
constexpr int C        = 64;               // channels
constexpr int GRID_DIM = 128;
constexpr int BATCH    = 4;
constexpr int VOXELS   = GRID_DIM * GRID_DIM * GRID_DIM * BATCH;  // 8,388,608

// Scan geometry: 1024 blocks * 256 threads * 32 items = 8,388,608 cells.
constexpr int SCAN_BLOCKS  = 1024;
constexpr int SCAN_THREADS = 256;
constexpr int SCAN_ITEMS   = 32;   // per thread

// ---------------------------------------------------------------------------
// Device scratch (no allocation allowed in kernel_launch).
// ---------------------------------------------------------------------------
__device__ int g_lin[N_PTS];        // point -> linear voxel id (fits int32)
__device__ int g_cnt[VOXELS];       // per-cell point count
__device__ int g_rank[VOXELS];      // per-cell rank; bit31 set => count>1
__device__ int g_bsum[SCAN_BLOCKS];
__device__ int g_boff[SCAN_BLOCKS];
__device__ int g_num_unique;
__device__ int g_is64;              // coords dtype: 1 = int64, 0 = int32

// ---------------------------------------------------------------------------
// Helpers
// ---------------------------------------------------------------------------
__device__ __forceinline__ int warp_incl_scan(int v) {
    #pragma unroll
    for (int d = 1; d < 32; d <<= 1) {
        int n = __shfl_up_sync(0xffffffffu, v, d);
        if ((threadIdx.x & 31) >= d) v += n;
    }
    return v;
}

// ---------------------------------------------------------------------------
// 0. Detect coords dtype: int64 coords have zero high words (values < 128).
// ---------------------------------------------------------------------------
__global__ void k_detect(const int* __restrict__ coords32) {
    if (threadIdx.x == 0 && blockIdx.x == 0) {
        int odd_nonzero = 0;
        #pragma unroll 8
        for (int i = 1; i < 2048; i += 2) odd_nonzero |= coords32[i];
        g_is64 = (odd_nonzero == 0) ? 1 : 0;
    }
}

// ---------------------------------------------------------------------------
// 1. Zero the count array (must happen every replay).
// ---------------------------------------------------------------------------
__global__ void k_zero_cnt() {
    int idx    = blockIdx.x * blockDim.x + threadIdx.x;
    int stride = gridDim.x * blockDim.x;
    int4* p = reinterpret_cast<int4*>(g_cnt);
    const int n4 = VOXELS / 4;
    for (int i = idx; i < n4; i += stride) p[i] = make_int4(0, 0, 0, 0);
}

// ---------------------------------------------------------------------------
// 2. Compute linear ids + per-cell counts.
//    lin = ((b*128 + x)*128 + y)*128 + z  (== b*vol + x*S1S2 + y*S2 + z)
// ---------------------------------------------------------------------------
__global__ void k_count(const void* __restrict__ coords) {
    int p = blockIdx.x * blockDim.x + threadIdx.x;
    if (p >= N_PTS) return;
    int x, y, z, b;
    if (g_is64) {
        const longlong4 v = reinterpret_cast<const longlong4*>(coords)[p];
        x = (int)v.x; y = (int)v.y; z = (int)v.z; b = (int)v.w;
    } else {
        const int4 v = reinterpret_cast<const int4*>(coords)[p];
        x = v.x; y = v.y; z = v.z; b = v.w;
    }
    int lin = ((b * GRID_DIM + x) * GRID_DIM + y) * GRID_DIM + z;
    g_lin[p] = lin;
    atomicAdd(&g_cnt[lin], 1);
}

// ---------------------------------------------------------------------------
// 3. Scan pass 1: per-block occupancy sums.
// ---------------------------------------------------------------------------
__global__ void k_scan1() {
    __shared__ int sh[SCAN_THREADS / 32];
    const int base = blockIdx.x * (SCAN_THREADS * SCAN_ITEMS) + threadIdx.x * SCAN_ITEMS;
    const int4* p = reinterpret_cast<const int4*>(g_cnt + base);
    int s = 0;
    #pragma unroll
    for (int k = 0; k < SCAN_ITEMS / 4; k++) {
        int4 v = p[k];
        s += (v.x != 0) + (v.y != 0) + (v.z != 0) + (v.w != 0);
    }
    int lane = threadIdx.x & 31, wid = threadIdx.x >> 5;
    #pragma unroll
    for (int d = 16; d; d >>= 1) s += __shfl_down_sync(0xffffffffu, s, d);
    if (lane == 0) sh[wid] = s;
    __syncthreads();
    if (threadIdx.x == 0) {
        int tot = 0;
        #pragma unroll
        for (int i = 0; i < SCAN_THREADS / 32; i++) tot += sh[i];
        g_bsum[blockIdx.x] = tot;
    }
}

// ---------------------------------------------------------------------------
// 4. Scan pass 2: exclusive scan of the 1024 block sums (single block).
// ---------------------------------------------------------------------------
__global__ void k_scan2() {
    __shared__ int sh[32];
    int t = threadIdx.x;                 // 1024 threads
    int v = g_bsum[t];
    int lane = t & 31, wid = t >> 5;
    int incl = warp_incl_scan(v);
    if (lane == 31) sh[wid] = incl;
    __syncthreads();
    if (wid == 0) {
        int w = sh[lane];
        w = warp_incl_scan(w);
        sh[lane] = w;
    }
    __syncthreads();
    int off = wid ? sh[wid - 1] : 0;
    g_boff[t] = off + incl - v;
    if (t == 1023) g_num_unique = off + incl;
}

// ---------------------------------------------------------------------------
// 5. Scan pass 3: per-cell ranks, write sorted unique ids, pre-zero the
//    output rows of multi-hit cells (so scatter can atomicAdd them).
// ---------------------------------------------------------------------------
__global__ void k_scan3(float* __restrict__ out_uniq, float* __restrict__ out_feat) {
    __shared__ int sh[SCAN_THREADS / 32];
    const int base = blockIdx.x * (SCAN_THREADS * SCAN_ITEMS) + threadIdx.x * SCAN_ITEMS;
    int cn[SCAN_ITEMS];
    const int4* p = reinterpret_cast<const int4*>(g_cnt + base);
    #pragma unroll
    for (int k = 0; k < SCAN_ITEMS / 4; k++) {
        int4 v = p[k];
        cn[4 * k + 0] = v.x; cn[4 * k + 1] = v.y;
        cn[4 * k + 2] = v.z; cn[4 * k + 3] = v.w;
    }
    int s = 0;
    #pragma unroll
    for (int k = 0; k < SCAN_ITEMS; k++) s += (cn[k] != 0);

    // block exclusive scan of thread sums
    int lane = threadIdx.x & 31, wid = threadIdx.x >> 5;
    int incl = warp_incl_scan(s);
    if (lane == 31) sh[wid] = incl;
    __syncthreads();
    if (wid == 0 && lane < SCAN_THREADS / 32) {
        int w = sh[lane];
        #pragma unroll
        for (int d = 1; d < SCAN_THREADS / 32; d <<= 1) {
            int n = __shfl_up_sync(0xffu, w, d);
            if (lane >= d) w += n;
        }
        sh[lane] = w;
    }
    __syncthreads();
    int warp_off = wid ? sh[wid - 1] : 0;
    int r = warp_off + incl - s + g_boff[blockIdx.x];

    #pragma unroll
    for (int k = 0; k < SCAN_ITEMS; k++) {
        int c = cn[k];
        if (c) {
            int i = base + k;
            out_uniq[r] = (float)i;                 // ids < 2^23: exact in fp32
            g_rank[i] = (c > 1) ? (r | 0x80000000) : r;
            if (c > 1) {
                float4 z = make_float4(0.f, 0.f, 0.f, 0.f);
                float4* row = reinterpret_cast<float4*>(out_feat + (size_t)r * C);
                #pragma unroll
                for (int j = 0; j < C / 4; j++) row[j] = z;
            }
            r++;
        }
    }
}

// ---------------------------------------------------------------------------
// 6. Tail: rows >= num_unique -> uniq = -1, feature row = 0.
//    16 threads per row, one float4 each.
// ---------------------------------------------------------------------------
__global__ void k_tail(float* __restrict__ out_uniq, float* __restrict__ out_feat) {
    int tid = blockIdx.x * blockDim.x + threadIdx.x;   // N_PTS*16 threads exactly
    int r = tid >> 4, t = tid & 15;
    if (r < g_num_unique) return;
    if (t == 0) out_uniq[r] = -1.0f;
    float4 z = make_float4(0.f, 0.f, 0.f, 0.f);
    reinterpret_cast<float4*>(out_feat + (size_t)r * C)[t] = z;
}

// ---------------------------------------------------------------------------
// 7. Feature scatter: plain store for unique cells, atomicAdd for multi cells.
//    16 threads per point, one float4 each.
// ---------------------------------------------------------------------------
__global__ void k_scatter(const float* __restrict__ feat, float* __restrict__ out_feat) {
    int tid = blockIdx.x * blockDim.x + threadIdx.x;   // N_PTS*16 threads exactly
    int pt = tid >> 4, t = tid & 15;
    int lin = g_lin[pt];
    int rr  = g_rank[lin];
    int r   = rr & 0x7fffffff;
    float4 v = reinterpret_cast<const float4*>(feat)[(size_t)pt * (C / 4) + t];
    float* dst = out_feat + (size_t)r * C + t * 4;
    if (rr >= 0) {
        *reinterpret_cast<float4*>(dst) = v;
    } else {
        atomicAdd(dst + 0, v.x);
        atomicAdd(dst + 1, v.y);
        atomicAdd(dst + 2, v.z);
        atomicAdd(dst + 3, v.w);
    }
}

// ---------------------------------------------------------------------------
// Launch
// ---------------------------------------------------------------------------
extern "C" void kernel_launch(void* const* d_in, const int* in_sizes, int n_in,
                              void* d_out, int out_size) {
    const void*  coords = d_in[0];                    // [N,4] int64 or int32
    const float* feats  = (const float*)d_in[1];      // [N,64] float32
    (void)in_sizes; (void)n_in; (void)out_size;

    float* out      = (float*)d_out;
    float* out_uniq = out;                            // [N]
    float* out_feat = out + N_PTS;                    // [N,64], 16B-aligned

    k_detect<<<1, 32>>>((const int*)coords);
    k_zero_cnt<<<2048, 256>>>();
    k_count<<<N_PTS / 256, 256>>>(coords);
    k_scan1<<<SCAN_BLOCKS, SCAN_THREADS>>>();
    k_scan2<<<1, 1024>>>();
    k_scan3<<<SCAN_BLOCKS, SCAN_THREADS>>>(out_uniq, out_feat);
    k_tail<<<(N_PTS * 16) / 256, 256>>>(out_uniq, out_feat);
    k_scatter<<<(N_PTS * 16) / 256, 256>>>(feats, out_feat);
}

// round 2
// speedup vs baseline: 1.1636x; 1.1636x over previous
#include <cuda_runtime.h>
#include <cstdint>

// Problem constants (fixed-shape problem).
constexpr int N_PTS    = 1048576;          // points
constexpr int C        = 64;               // channels
constexpr int GRID_DIM = 128;
constexpr int BATCH    = 4;
constexpr int VOXELS   = GRID_DIM * GRID_DIM * GRID_DIM * BATCH;  // 8,388,608
constexpr int WORDS    = VOXELS / 64;                             // 131,072

// Word-scan geometry: 256 blocks * 256 threads * 2 words = 131,072 words.
constexpr int WSCAN_BLOCKS  = 256;
constexpr int WSCAN_THREADS = 256;

// ---------------------------------------------------------------------------
// Device scratch (no allocation allowed in kernel_launch).
// ---------------------------------------------------------------------------
__device__ int                g_lin[N_PTS];       // point -> linear voxel id
__device__ unsigned long long g_bm[WORDS];        // occupancy bitmap   (1 MB)
__device__ unsigned long long g_mb[WORDS];        // multi-hit bitmap   (1 MB)
__device__ int                g_wordoff[WORDS];   // excl. rank prefix per word
__device__ int                g_bsum[WSCAN_BLOCKS];
__device__ int                g_boff[WSCAN_BLOCKS];
__device__ int                g_num_unique;
__device__ int                g_is64;             // coords dtype flag

// ---------------------------------------------------------------------------
__device__ __forceinline__ int warp_incl_scan(int v) {
    #pragma unroll
    for (int d = 1; d < 32; d <<= 1) {
        int n = __shfl_up_sync(0xffffffffu, v, d);
        if ((threadIdx.x & 31) >= d) v += n;
    }
    return v;
}

// 0. Detect coords dtype: int64 coords (<128) have zero high words.
__global__ void k_detect(const int* __restrict__ coords32) {
    if (threadIdx.x == 0 && blockIdx.x == 0) {
        int odd_nonzero = 0;
        #pragma unroll 8
        for (int i = 1; i < 2048; i += 2) odd_nonzero |= coords32[i];
        g_is64 = (odd_nonzero == 0) ? 1 : 0;
    }
}

// 1. Zero both bitmaps (2 MB total) — every replay.
__global__ void k_zero_bm() {
    int idx    = blockIdx.x * blockDim.x + threadIdx.x;
    int stride = gridDim.x * blockDim.x;
    ulonglong2 z = make_ulonglong2(0ull, 0ull);
    ulonglong2* p0 = reinterpret_cast<ulonglong2*>(g_bm);
    ulonglong2* p1 = reinterpret_cast<ulonglong2*>(g_mb);
    const int n2 = WORDS / 2;
    for (int i = idx; i < n2; i += stride) { p0[i] = z; p1[i] = z; }
}

// 2. lin ids + occupancy/multi bitmaps.
__global__ void k_count(const void* __restrict__ coords) {
    int p = blockIdx.x * blockDim.x + threadIdx.x;
    if (p >= N_PTS) return;
    int x, y, z, b;
    if (g_is64) {
        const longlong4 v = reinterpret_cast<const longlong4*>(coords)[p];
        x = (int)v.x; y = (int)v.y; z = (int)v.z; b = (int)v.w;
    } else {
        const int4 v = reinterpret_cast<const int4*>(coords)[p];
        x = v.x; y = v.y; z = v.z; b = v.w;
    }
    int lin = ((b * GRID_DIM + x) * GRID_DIM + y) * GRID_DIM + z;
    g_lin[p] = lin;
    unsigned long long mask = 1ull << (lin & 63);
    unsigned long long old  = atomicOr(&g_bm[lin >> 6], mask);
    if (old & mask) atomicOr(&g_mb[lin >> 6], mask);   // second+ arrival
}

// 3. Scan pass 1: per-block popcount sums (each block: 512 words).
__global__ void k_scan1() {
    __shared__ int sh[WSCAN_THREADS / 32];
    int w0 = blockIdx.x * (WSCAN_THREADS * 2) + threadIdx.x * 2;
    ulonglong2 v = reinterpret_cast<const ulonglong2*>(g_bm)[w0 >> 1];
    int s = __popcll(v.x) + __popcll(v.y);
    int lane = threadIdx.x & 31, wid = threadIdx.x >> 5;
    #pragma unroll
    for (int d = 16; d; d >>= 1) s += __shfl_down_sync(0xffffffffu, s, d);
    if (lane == 0) sh[wid] = s;
    __syncthreads();
    if (threadIdx.x == 0) {
        int tot = 0;
        #pragma unroll
        for (int i = 0; i < WSCAN_THREADS / 32; i++) tot += sh[i];
        g_bsum[blockIdx.x] = tot;
    }
}

// 4. Scan pass 2: exclusive scan of 256 block sums (one block).
__global__ void k_scan2() {
    __shared__ int sh[8];
    int t = threadIdx.x;                       // 256 threads
    int v = g_bsum[t];
    int lane = t & 31, wid = t >> 5;
    int incl = warp_incl_scan(v);
    if (lane == 31) sh[wid] = incl;
    __syncthreads();
    if (wid == 0 && lane < 8) {
        int w = sh[lane];
        #pragma unroll
        for (int d = 1; d < 8; d <<= 1) {
            int n = __shfl_up_sync(0xffu, w, d);
            if (lane >= d) w += n;
        }
        sh[lane] = w;
    }
    __syncthreads();
    int off = wid ? sh[wid - 1] : 0;
    g_boff[t] = off + incl - v;
    if (t == 255) g_num_unique = off + incl;
}

// 5. Scan pass 3: per-word offsets, sorted unique ids, pre-zero multi rows.
__global__ void k_scan3(float* __restrict__ out_uniq, float* __restrict__ out_feat) {
    __shared__ int sh[WSCAN_THREADS / 32];
    int w0 = blockIdx.x * (WSCAN_THREADS * 2) + threadIdx.x * 2;
    ulonglong2 bmv = reinterpret_cast<const ulonglong2*>(g_bm)[w0 >> 1];
    int p0 = __popcll(bmv.x), p1 = __popcll(bmv.y);
    int s = p0 + p1;

    int lane = threadIdx.x & 31, wid = threadIdx.x >> 5;
    int incl = warp_incl_scan(s);
    if (lane == 31) sh[wid] = incl;
    __syncthreads();
    if (wid == 0 && lane < WSCAN_THREADS / 32) {
        int w = sh[lane];
        #pragma unroll
        for (int d = 1; d < WSCAN_THREADS / 32; d <<= 1) {
            int n = __shfl_up_sync(0xffu, w, d);
            if (lane >= d) w += n;
        }
        sh[lane] = w;
    }
    __syncthreads();
    int warp_off = wid ? sh[wid - 1] : 0;
    int off = g_boff[blockIdx.x] + warp_off + incl - s;

    g_wordoff[w0]     = off;
    g_wordoff[w0 + 1] = off + p0;

    ulonglong2 mbv = reinterpret_cast<const ulonglong2*>(g_mb)[w0 >> 1];
    #pragma unroll
    for (int half = 0; half < 2; half++) {
        unsigned long long bm = half ? bmv.y : bmv.x;
        unsigned long long mb = half ? mbv.y : mbv.x;
        int w = w0 + half;
        int r = half ? (off + p0) : off;
        while (bm) {
            int b = __ffsll((long long)bm) - 1;
            bm &= bm - 1;
            int cell = (w << 6) | b;
            out_uniq[r] = (float)cell;              // ids < 2^23: exact in fp32
            if ((mb >> b) & 1) {                    // multi-hit: pre-zero row
                float4 zz = make_float4(0.f, 0.f, 0.f, 0.f);
                float4* row = reinterpret_cast<float4*>(out_feat + (size_t)r * C);
                #pragma unroll
                for (int j = 0; j < C / 4; j++) row[j] = zz;
            }
            r++;
        }
    }
}

// 6. Tail: rows >= num_unique -> uniq = -1, feature row = 0.
__global__ void k_tail(float* __restrict__ out_uniq, float* __restrict__ out_feat) {
    int tid = blockIdx.x * blockDim.x + threadIdx.x;   // N_PTS*16 threads
    int r = tid >> 4, t = tid & 15;
    if (r < g_num_unique) return;
    if (t == 0) out_uniq[r] = -1.0f;
    float4 z = make_float4(0.f, 0.f, 0.f, 0.f);
    reinterpret_cast<float4*>(out_feat + (size_t)r * C)[t] = z;
}

// 7. Feature scatter. 16 threads per point; rank computed by lanes 0/16 and
//    broadcast via shuffle. Plain store for unique cells, atomicAdd for multi.
__global__ void k_scatter(const float* __restrict__ feat, float* __restrict__ out_feat) {
    int tid  = blockIdx.x * blockDim.x + threadIdx.x;  // N_PTS*16 threads
    int pt   = tid >> 4, t = tid & 15;
    int lane = threadIdx.x & 31;

    int rr = 0;
    if ((lane & 15) == 0) {
        int lin  = g_lin[pt];
        int w    = lin >> 6, b = lin & 63;
        unsigned long long bm = g_bm[w];
        int r = g_wordoff[w] + __popcll(bm & ((1ull << b) - 1ull));
        unsigned long long mb = g_mb[w];
        rr = r | (int)(((mb >> b) & 1ull) << 31);
    }
    rr = __shfl_sync(0xffffffffu, rr, lane & 16);

    int r = rr & 0x7fffffff;
    float4 v = reinterpret_cast<const float4*>(feat)[(size_t)pt * (C / 4) + t];
    float* dst = out_feat + (size_t)r * C + t * 4;
    if (rr >= 0) {
        *reinterpret_cast<float4*>(dst) = v;
    } else {
        atomicAdd(dst + 0, v.x);
        atomicAdd(dst + 1, v.y);
        atomicAdd(dst + 2, v.z);
        atomicAdd(dst + 3, v.w);
    }
}

// ---------------------------------------------------------------------------
extern "C" void kernel_launch(void* const* d_in, const int* in_sizes, int n_in,
                              void* d_out, int out_size) {
    const void*  coords = d_in[0];                    // [N,4] int64 or int32
    const float* feats  = (const float*)d_in[1];      // [N,64] float32
    (void)in_sizes; (void)n_in; (void)out_size;

    float* out      = (float*)d_out;
    float* out_uniq = out;                            // [N]
    float* out_feat = out + N_PTS;                    // [N,64], 16B-aligned

    k_detect<<<1, 32>>>((const int*)coords);
    k_zero_bm<<<256, 256>>>();
    k_count<<<N_PTS / 256, 256>>>(coords);
    k_scan1<<<WSCAN_BLOCKS, WSCAN_THREADS>>>();
    k_scan2<<<1, 256>>>();
    k_scan3<<<WSCAN_BLOCKS, WSCAN_THREADS>>>(out_uniq, out_feat);
    k_tail<<<(N_PTS * 16) / 256, 256>>>(out_uniq, out_feat);
    k_scatter<<<(N_PTS * 16) / 256, 256>>>(feats, out_feat);
}

// round 3
// speedup vs baseline: 1.8553x; 1.5944x over previous
#include <cuda_runtime.h>
#include <cstdint>

// Problem constants (fixed-shape problem).
constexpr int N_PTS    = 1048576;          // points
constexpr int C        = 64;               // channels
constexpr int GRID_DIM = 128;
constexpr int BATCH    = 4;
constexpr int VOXELS   = GRID_DIM * GRID_DIM * GRID_DIM * BATCH;  // 8,388,608
constexpr int WORDS    = VOXELS / 64;                             // 131,072

constexpr int WSCAN_BLOCKS  = 256;
constexpr int WSCAN_THREADS = 256;

// ---------------------------------------------------------------------------
// Device scratch.
// ---------------------------------------------------------------------------
__device__ int                g_lin[N_PTS];       // point -> linear voxel id
__device__ unsigned long long g_bm[WORDS];        // occupancy bitmap   (1 MB)
__device__ unsigned long long g_mb[WORDS];        // multi-hit bitmap   (1 MB)
__device__ int                g_wordoff[WORDS];   // excl. rank prefix per word
__device__ int                g_bsum[WSCAN_BLOCKS];
__device__ int                g_boff[WSCAN_BLOCKS];
__device__ int                g_num_unique;
__device__ int                g_is64;             // coords dtype flag

// ---------------------------------------------------------------------------
__device__ __forceinline__ int warp_incl_scan(int v) {
    #pragma unroll
    for (int d = 1; d < 32; d <<= 1) {
        int n = __shfl_up_sync(0xffffffffu, v, d);
        if ((threadIdx.x & 31) >= d) v += n;
    }
    return v;
}

// ---------------------------------------------------------------------------
// 1. Zero both bitmaps + parallel dtype detect (block 0, warp 0).
//    int64 coords (values < 128) have all-zero high 32-bit words.
// ---------------------------------------------------------------------------
__global__ void k_init(const int* __restrict__ coords32) {
    int idx    = blockIdx.x * blockDim.x + threadIdx.x;
    int stride = gridDim.x * blockDim.x;
    ulonglong2 z = make_ulonglong2(0ull, 0ull);
    ulonglong2* p0 = reinterpret_cast<ulonglong2*>(g_bm);
    ulonglong2* p1 = reinterpret_cast<ulonglong2*>(g_mb);
    const int n2 = WORDS / 2;
    for (int i = idx; i < n2; i += stride) { p0[i] = z; p1[i] = z; }

    if (blockIdx.x == 0 && threadIdx.x < 32) {
        int lane = threadIdx.x;
        int acc = 0;
        #pragma unroll
        for (int k = 0; k < 32; k++)                 // odd words of first 2048 ints
            acc |= coords32[1 + 2 * (lane + 32 * k)];
        #pragma unroll
        for (int d = 16; d; d >>= 1) acc |= __shfl_down_sync(0xffffffffu, acc, d);
        if (lane == 0) g_is64 = (acc == 0) ? 1 : 0;
    }
}

// ---------------------------------------------------------------------------
// 2. lin ids + occupancy / multi-hit bitmaps.
// ---------------------------------------------------------------------------
__global__ void k_count(const void* __restrict__ coords) {
    int p = blockIdx.x * blockDim.x + threadIdx.x;
    if (p >= N_PTS) return;
    int x, y, z, b;
    if (g_is64) {
        const longlong4 v = reinterpret_cast<const longlong4*>(coords)[p];
        x = (int)v.x; y = (int)v.y; z = (int)v.z; b = (int)v.w;
    } else {
        const int4 v = reinterpret_cast<const int4*>(coords)[p];
        x = v.x; y = v.y; z = v.z; b = v.w;
    }
    int lin = ((b * GRID_DIM + x) * GRID_DIM + y) * GRID_DIM + z;
    g_lin[p] = lin;
    unsigned long long mask = 1ull << (lin & 63);
    unsigned long long old  = atomicOr(&g_bm[lin >> 6], mask);
    if (old & mask) atomicOr(&g_mb[lin >> 6], mask);   // second+ arrival
}

// ---------------------------------------------------------------------------
// 3. Scan pass 1: per-block popcount sums (512 words / block).
// ---------------------------------------------------------------------------
__global__ void k_scan1() {
    __shared__ int sh[WSCAN_THREADS / 32];
    int w0 = blockIdx.x * (WSCAN_THREADS * 2) + threadIdx.x * 2;
    ulonglong2 v = reinterpret_cast<const ulonglong2*>(g_bm)[w0 >> 1];
    int s = __popcll(v.x) + __popcll(v.y);
    int lane = threadIdx.x & 31, wid = threadIdx.x >> 5;
    #pragma unroll
    for (int d = 16; d; d >>= 1) s += __shfl_down_sync(0xffffffffu, s, d);
    if (lane == 0) sh[wid] = s;
    __syncthreads();
    if (threadIdx.x == 0) {
        int tot = 0;
        #pragma unroll
        for (int i = 0; i < WSCAN_THREADS / 32; i++) tot += sh[i];
        g_bsum[blockIdx.x] = tot;
    }
}

// ---------------------------------------------------------------------------
// 4. Scan pass 2: exclusive scan of 256 block sums.
// ---------------------------------------------------------------------------
__global__ void k_scan2() {
    __shared__ int sh[8];
    int t = threadIdx.x;                       // 256 threads
    int v = g_bsum[t];
    int lane = t & 31, wid = t >> 5;
    int incl = warp_incl_scan(v);
    if (lane == 31) sh[wid] = incl;
    __syncthreads();
    if (wid == 0 && lane < 8) {
        int w = sh[lane];
        #pragma unroll
        for (int d = 1; d < 8; d <<= 1) {
            int n = __shfl_up_sync(0xffu, w, d);
            if (lane >= d) w += n;
        }
        sh[lane] = w;
    }
    __syncthreads();
    int off = wid ? sh[wid - 1] : 0;
    g_boff[t] = off + incl - v;
    if (t == 255) g_num_unique = off + incl;
}

// ---------------------------------------------------------------------------
// 5. Scan pass 3: per-word offsets, sorted unique ids, pre-zero multi rows.
// ---------------------------------------------------------------------------
__global__ void k_scan3(float* __restrict__ out_uniq, float* __restrict__ out_feat) {
    __shared__ int sh[WSCAN_THREADS / 32];
    int w0 = blockIdx.x * (WSCAN_THREADS * 2) + threadIdx.x * 2;
    ulonglong2 bmv = reinterpret_cast<const ulonglong2*>(g_bm)[w0 >> 1];
    int p0 = __popcll(bmv.x), p1 = __popcll(bmv.y);
    int s = p0 + p1;

    int lane = threadIdx.x & 31, wid = threadIdx.x >> 5;
    int incl = warp_incl_scan(s);
    if (lane == 31) sh[wid] = incl;
    __syncthreads();
    if (wid == 0 && lane < WSCAN_THREADS / 32) {
        int w = sh[lane];
        #pragma unroll
        for (int d = 1; d < WSCAN_THREADS / 32; d <<= 1) {
            int n = __shfl_up_sync(0xffu, w, d);
            if (lane >= d) w += n;
        }
        sh[lane] = w;
    }
    __syncthreads();
    int warp_off = wid ? sh[wid - 1] : 0;
    int off = g_boff[blockIdx.x] + warp_off + incl - s;

    g_wordoff[w0]     = off;
    g_wordoff[w0 + 1] = off + p0;

    ulonglong2 mbv = reinterpret_cast<const ulonglong2*>(g_mb)[w0 >> 1];
    #pragma unroll
    for (int half = 0; half < 2; half++) {
        unsigned long long bm = half ? bmv.y : bmv.x;
        unsigned long long mb = half ? mbv.y : mbv.x;
        int w = w0 + half;
        int r = half ? (off + p0) : off;
        while (bm) {
            int b = __ffsll((long long)bm) - 1;
            bm &= bm - 1;
            int cell = (w << 6) | b;
            out_uniq[r] = (float)cell;              // ids < 2^23: exact in fp32
            if ((mb >> b) & 1) {                    // multi-hit: pre-zero row
                float4 zz = make_float4(0.f, 0.f, 0.f, 0.f);
                float4* row = reinterpret_cast<float4*>(out_feat + (size_t)r * C);
                #pragma unroll
                for (int j = 0; j < C / 4; j++) row[j] = zz;
            }
            r++;
        }
    }
}

// ---------------------------------------------------------------------------
// 6. Scatter + tail merged. 8 threads per point, 2 float4 each.
//    Streaming cache hints (no reuse of the 512 MB feature stream).
// ---------------------------------------------------------------------------
__global__ void k_scatter(const float* __restrict__ feat,
                          float* __restrict__ out_uniq,
                          float* __restrict__ out_feat) {
    int tid  = blockIdx.x * blockDim.x + threadIdx.x;   // N_PTS * 8 threads
    int pt   = tid >> 3, t = tid & 7;
    int lane = threadIdx.x & 31;

    // ---- tail: rows >= num_unique -> uniq=-1, feature row = 0 ----
    int nu = g_num_unique;
    if (pt >= nu) {
        if (t == 0) out_uniq[pt] = -1.0f;
        float4 z = make_float4(0.f, 0.f, 0.f, 0.f);
        float4* row = reinterpret_cast<float4*>(out_feat + (size_t)pt * C);
        __stcs(&row[2 * t], z);
        __stcs(&row[2 * t + 1], z);
    }

    // ---- rank for this point (computed on lanes 0,8,16,24; broadcast) ----
    int rr = 0;
    if ((lane & 7) == 0) {
        int lin = g_lin[pt];
        int w   = lin >> 6, b = lin & 63;
        unsigned long long bm = g_bm[w];
        int r = g_wordoff[w] + __popcll(bm & ((1ull << b) - 1ull));
        unsigned long long mb = g_mb[w];
        rr = r | (int)(((mb >> b) & 1ull) << 31);
    }
    rr = __shfl_sync(0xffffffffu, rr, lane & 24);

    int r = rr & 0x7fffffff;
    const float4* src = reinterpret_cast<const float4*>(feat) + (size_t)pt * (C / 4);
    float4 v0 = __ldcs(&src[2 * t]);
    float4 v1 = __ldcs(&src[2 * t + 1]);
    float* dst = out_feat + (size_t)r * C + t * 8;
    if (rr >= 0) {
        __stcs(reinterpret_cast<float4*>(dst),     v0);
        __stcs(reinterpret_cast<float4*>(dst) + 1, v1);
    } else {
        atomicAdd(dst + 0, v0.x); atomicAdd(dst + 1, v0.y);
        atomicAdd(dst + 2, v0.z); atomicAdd(dst + 3, v0.w);
        atomicAdd(dst + 4, v1.x); atomicAdd(dst + 5, v1.y);
        atomicAdd(dst + 6, v1.z); atomicAdd(dst + 7, v1.w);
    }
}

// ---------------------------------------------------------------------------
extern "C" void kernel_launch(void* const* d_in, const int* in_sizes, int n_in,
                              void* d_out, int out_size) {
    const void*  coords = d_in[0];                    // [N,4] int64 or int32
    const float* feats  = (const float*)d_in[1];      // [N,64] float32
    (void)in_sizes; (void)n_in; (void)out_size;

    float* out      = (float*)d_out;
    float* out_uniq = out;                            // [N]
    float* out_feat = out + N_PTS;                    // [N,64], 16B-aligned

    k_init<<<256, 256>>>((const int*)coords);
    k_count<<<N_PTS / 256, 256>>>(coords);
    k_scan1<<<WSCAN_BLOCKS, WSCAN_THREADS>>>();
    k_scan2<<<1, 256>>>();
    k_scan3<<<WSCAN_BLOCKS, WSCAN_THREADS>>>(out_uniq, out_feat);
    k_scatter<<<(N_PTS * 8) / 256, 256>>>(feats, out_uniq, out_feat);
}